// round 2
// baseline (speedup 1.0000x reference)
#include <cuda_runtime.h>

// Problem constants
#define NB 4
#define TT 2048
#define DD 512
#define HH 8
#define HDIM 64
#define MROWS (NB * TT)   // 8192

// Scratch (allocation-free: __device__ globals)
__device__ float g_keys[NB * TT * DD];
__device__ float g_vals[NB * TT * DD];
__device__ float g_attn[NB * TT * DD];

// ---------------------------------------------------------------------------
// SGEMM NT: C[M,Nc] = A[M,K] @ B[Nc,K]^T  (+ optional residual A[M,Nc])
// BM=BN=128, BK=16, 256 threads, 8x8 per-thread microtile.
// ---------------------------------------------------------------------------
template <bool RESIDUAL>
__global__ __launch_bounds__(256, 2) void sgemm_nt(const float* __restrict__ A,
                                                   const float* __restrict__ B,
                                                   float* __restrict__ C,
                                                   int K, int Ncols) {
    constexpr int BM = 128, BN = 128, BK = 16;
    __shared__ float As[BK * BM];
    __shared__ float Bs[BK * BN];

    const int tid = threadIdx.x;
    const int tx = tid & 15;          // 0..15  (N direction)
    const int ty = tid >> 4;          // 0..15  (M direction)
    const int bm = blockIdx.x * BM;
    const int bn = blockIdx.y * BN;

    float acc[8][8];
#pragma unroll
    for (int i = 0; i < 8; i++)
#pragma unroll
        for (int j = 0; j < 8; j++) acc[i][j] = 0.f;

    for (int k0 = 0; k0 < K; k0 += BK) {
        // Load A and B tiles (128x16 each) as float4 along K, store transposed [k][m]
#pragma unroll
        for (int it = 0; it < 2; it++) {
            int i  = tid + it * 256;       // 0..511 (float4 index)
            int r  = i >> 2;               // 0..127
            int c4 = (i & 3) << 2;         // 0,4,8,12
            float4 va = *(const float4*)(A + (size_t)(bm + r) * K + k0 + c4);
            As[(c4 + 0) * BM + r] = va.x;
            As[(c4 + 1) * BM + r] = va.y;
            As[(c4 + 2) * BM + r] = va.z;
            As[(c4 + 3) * BM + r] = va.w;
            float4 vb = *(const float4*)(B + (size_t)(bn + r) * K + k0 + c4);
            Bs[(c4 + 0) * BN + r] = vb.x;
            Bs[(c4 + 1) * BN + r] = vb.y;
            Bs[(c4 + 2) * BN + r] = vb.z;
            Bs[(c4 + 3) * BN + r] = vb.w;
        }
        __syncthreads();

#pragma unroll
        for (int k = 0; k < BK; k++) {
            float a[8], b[8];
            *(float4*)(a)     = *(const float4*)&As[k * BM + ty * 8];
            *(float4*)(a + 4) = *(const float4*)&As[k * BM + ty * 8 + 4];
            *(float4*)(b)     = *(const float4*)&Bs[k * BN + tx * 8];
            *(float4*)(b + 4) = *(const float4*)&Bs[k * BN + tx * 8 + 4];
#pragma unroll
            for (int i = 0; i < 8; i++)
#pragma unroll
                for (int j = 0; j < 8; j++) acc[i][j] += a[i] * b[j];
        }
        __syncthreads();
    }

    // Epilogue (vectorized). RESIDUAL requires Ncols == K (true here: 512).
#pragma unroll
    for (int i = 0; i < 8; i++) {
        int row = bm + ty * 8 + i;
        float* crow = C + (size_t)row * Ncols + bn + tx * 8;
#pragma unroll
        for (int j = 0; j < 8; j += 4) {
            float4 v = make_float4(acc[i][j], acc[i][j + 1], acc[i][j + 2], acc[i][j + 3]);
            if (RESIDUAL) {
                float4 rr = *(const float4*)(A + (size_t)row * K + bn + tx * 8 + j);
                v.x += rr.x; v.y += rr.y; v.z += rr.z; v.w += rr.w;
            }
            *(float4*)(crow + j) = v;
        }
    }
}

// ---------------------------------------------------------------------------
// Flash attention, fp32. One block = 64 query rows of one (n,h) pair.
// Streams over 32 KV tiles of 64 tokens. 256 threads (16x16), 4x4 microtiles.
// Q pre-scaled by 1/sqrt(HD)=0.125. Online softmax with 16-lane shfl reduce.
// ---------------------------------------------------------------------------
#define BQ 64
#define BKV 64
#define KT_STRIDE 65   // padded stride for transposed K tile (conflict-free)

// dynamic smem layout (floats):
//   Qs  [64*64]          16384 B
//   Kts [64*65]          16640 B   ([d][token], padded)
//   Vs  [64*64]          16384 B   ([token][d])
//   Ps  [64*64]          16384 B
#define FLASH_SMEM_FLOATS (64 * 64 + 64 * KT_STRIDE + 64 * 64 + 64 * 64)
#define FLASH_SMEM_BYTES (FLASH_SMEM_FLOATS * 4)

__global__ __launch_bounds__(256, 2) void flash_attn(const float* __restrict__ Q) {
    extern __shared__ float sm[];
    float* Qs  = sm;
    float* Kts = Qs + 64 * 64;
    float* Vs  = Kts + 64 * KT_STRIDE;
    float* Ps  = Vs + 64 * 64;

    const int tid = threadIdx.x;
    const int tx = tid & 15;
    const int ty = tid >> 4;
    const int r0 = ty * 4;     // query-row offset inside tile
    const int c0 = tx * 4;     // (kv-token | head-dim) column offset

    const int qt = blockIdx.x;             // query tile index (0..31)
    const int nh = blockIdx.y;             // n*H + h (0..31)
    const int n = nh >> 3;                 // H == 8
    const int h = nh & 7;

    const float* Qbase = Q      + (size_t)n * TT * DD + (size_t)(qt * BQ) * DD + h * HDIM;
    const float* Kbase = g_keys + (size_t)n * TT * DD + h * HDIM;
    const float* Vbase = g_vals + (size_t)n * TT * DD + h * HDIM;

    // Load Q tile (pre-scaled by 1/sqrt(HD))
    for (int i = tid; i < BQ * HDIM; i += 256) {
        int r = i >> 6, d = i & 63;
        Qs[r * 64 + d] = Qbase[(size_t)r * DD + d] * 0.125f;
    }

    float m[4], l[4], o[4][4];
#pragma unroll
    for (int i = 0; i < 4; i++) {
        m[i] = -1e30f;
        l[i] = 0.f;
#pragma unroll
        for (int j = 0; j < 4; j++) o[i][j] = 0.f;
    }

    for (int kt = 0; kt < TT / BKV; kt++) {
        const float* Kt = Kbase + (size_t)(kt * BKV) * DD;
        const float* Vt = Vbase + (size_t)(kt * BKV) * DD;

        __syncthreads();   // prior iter's PV reads of Vs done; Qs ready (iter 0)
        // Load K (transposed, padded) and V (row-major). Coalesced global reads,
        // conflict-free smem writes (Kts stride 65; Vs consecutive).
        for (int i = tid; i < BKV * HDIM; i += 256) {
            int tok = i >> 6, d = i & 63;
            Kts[d * KT_STRIDE + tok] = Kt[(size_t)tok * DD + d];
            Vs[tok * 64 + d]         = Vt[(size_t)tok * DD + d];
        }
        __syncthreads();

        // S = Qs @ Kts   (4x4 per thread)
        float s[4][4];
#pragma unroll
        for (int i = 0; i < 4; i++)
#pragma unroll
            for (int j = 0; j < 4; j++) s[i][j] = 0.f;

        for (int d4 = 0; d4 < HDIM; d4 += 4) {
            float qa[4][4];
#pragma unroll
            for (int i = 0; i < 4; i++) {
                float4 t = *(const float4*)&Qs[(r0 + i) * 64 + d4];
                qa[i][0] = t.x; qa[i][1] = t.y; qa[i][2] = t.z; qa[i][3] = t.w;
            }
#pragma unroll
            for (int u = 0; u < 4; u++) {
                const float* krow = &Kts[(d4 + u) * KT_STRIDE + c0];
                float kb[4];
#pragma unroll
                for (int j = 0; j < 4; j++) kb[j] = krow[j];
#pragma unroll
                for (int i = 0; i < 4; i++)
#pragma unroll
                    for (int j = 0; j < 4; j++) s[i][j] += qa[i][u] * kb[j];
            }
        }

        // Online softmax (per row, reduced across the 16 tx lanes)
#pragma unroll
        for (int i = 0; i < 4; i++) {
            float rm = fmaxf(fmaxf(s[i][0], s[i][1]), fmaxf(s[i][2], s[i][3]));
            rm = fmaxf(rm, __shfl_xor_sync(0xffffffffu, rm, 1, 16));
            rm = fmaxf(rm, __shfl_xor_sync(0xffffffffu, rm, 2, 16));
            rm = fmaxf(rm, __shfl_xor_sync(0xffffffffu, rm, 4, 16));
            rm = fmaxf(rm, __shfl_xor_sync(0xffffffffu, rm, 8, 16));
            float mn = fmaxf(m[i], rm);
            float corr = __expf(m[i] - mn);
            float ps = 0.f;
#pragma unroll
            for (int j = 0; j < 4; j++) {
                s[i][j] = __expf(s[i][j] - mn);
                ps += s[i][j];
            }
            ps += __shfl_xor_sync(0xffffffffu, ps, 1, 16);
            ps += __shfl_xor_sync(0xffffffffu, ps, 2, 16);
            ps += __shfl_xor_sync(0xffffffffu, ps, 4, 16);
            ps += __shfl_xor_sync(0xffffffffu, ps, 8, 16);
            l[i] = l[i] * corr + ps;
            m[i] = mn;
#pragma unroll
            for (int j = 0; j < 4; j++) o[i][j] *= corr;
        }

        // Stage P tile (vectorized, conflict-free)
#pragma unroll
        for (int i = 0; i < 4; i++)
            *(float4*)&Ps[(r0 + i) * 64 + c0] =
                make_float4(s[i][0], s[i][1], s[i][2], s[i][3]);
        __syncthreads();

        // O += P @ V
        for (int t4 = 0; t4 < BKV; t4 += 4) {
            float pa[4][4];
#pragma unroll
            for (int i = 0; i < 4; i++) {
                float4 t = *(const float4*)&Ps[(r0 + i) * 64 + t4];
                pa[i][0] = t.x; pa[i][1] = t.y; pa[i][2] = t.z; pa[i][3] = t.w;
            }
#pragma unroll
            for (int u = 0; u < 4; u++) {
                float4 vb = *(const float4*)&Vs[(t4 + u) * 64 + c0];
#pragma unroll
                for (int i = 0; i < 4; i++) {
                    o[i][0] += pa[i][u] * vb.x;
                    o[i][1] += pa[i][u] * vb.y;
                    o[i][2] += pa[i][u] * vb.z;
                    o[i][3] += pa[i][u] * vb.w;
                }
            }
        }
    }

    // Epilogue: normalize and store head output (concat layout matches reference)
    float* Ob = g_attn + (size_t)n * TT * DD + (size_t)(qt * BQ) * DD + h * HDIM;
#pragma unroll
    for (int i = 0; i < 4; i++) {
        float inv = 1.0f / l[i];
        *(float4*)&Ob[(size_t)(r0 + i) * DD + c0] =
            make_float4(o[i][0] * inv, o[i][1] * inv, o[i][2] * inv, o[i][3] * inv);
    }
}

// ---------------------------------------------------------------------------
// Launch
// ---------------------------------------------------------------------------
extern "C" void kernel_launch(void* const* d_in, const int* in_sizes, int n_in,
                              void* d_out, int out_size) {
    const float* q  = (const float*)d_in[0];
    const float* Wk = (const float*)d_in[1];
    const float* Wv = (const float*)d_in[2];
    const float* Wo = (const float*)d_in[3];
    float* out = (float*)d_out;

    float *keys, *vals, *attn;
    cudaGetSymbolAddress((void**)&keys, g_keys);
    cudaGetSymbolAddress((void**)&vals, g_vals);
    cudaGetSymbolAddress((void**)&attn, g_attn);

    dim3 gGemm(MROWS / 128, DD / 128);   // (64, 4)

    // keys = q @ Wk^T + q ; vals = q @ Wv^T
    sgemm_nt<true ><<<gGemm, 256>>>(q, Wk, keys, DD, DD);
    sgemm_nt<false><<<gGemm, 256>>>(q, Wv, vals, DD, DD);

    // flash attention over heads
    cudaFuncSetAttribute(flash_attn, cudaFuncAttributeMaxDynamicSharedMemorySize,
                         FLASH_SMEM_BYTES);
    dim3 gFlash(TT / BQ, NB * HH);       // (32, 32)
    flash_attn<<<gFlash, 256, FLASH_SMEM_BYTES>>>(q);

    // out = attn @ Wo^T
    sgemm_nt<false><<<gGemm, 256>>>(attn, Wo, out, DD, DD);
}

// round 4
// speedup vs baseline: 1.0547x; 1.0547x over previous
#include <cuda_runtime.h>

// Problem constants
#define NB 4
#define TT 2048
#define DD 512
#define HH 8
#define HDIM 64
#define MROWS (NB * TT)   // 8192

// Scratch (allocation-free: __device__ globals)
__device__ float g_keys[NB * TT * DD];
__device__ float g_vals[NB * TT * DD];
__device__ float g_attn[NB * TT * DD];

// ---------------------------------------------------------------------------
// SGEMM NT: C[M,Nc] = A[M,K] @ B[Nc,K]^T  (+ optional residual A[M,Nc])
// BM=BN=128, BK=16, 256 threads, 8x8 per-thread microtile. (proven in R2)
// ---------------------------------------------------------------------------
template <bool RESIDUAL>
__global__ __launch_bounds__(256, 2) void sgemm_nt(const float* __restrict__ A,
                                                   const float* __restrict__ B,
                                                   float* __restrict__ C,
                                                   int K, int Ncols) {
    constexpr int BM = 128, BN = 128, BK = 16;
    __shared__ float As[BK * BM];
    __shared__ float Bs[BK * BN];

    const int tid = threadIdx.x;
    const int tx = tid & 15;          // 0..15  (N direction)
    const int ty = tid >> 4;          // 0..15  (M direction)
    const int bm = blockIdx.x * BM;
    const int bn = blockIdx.y * BN;

    float acc[8][8];
#pragma unroll
    for (int i = 0; i < 8; i++)
#pragma unroll
        for (int j = 0; j < 8; j++) acc[i][j] = 0.f;

    for (int k0 = 0; k0 < K; k0 += BK) {
#pragma unroll
        for (int it = 0; it < 2; it++) {
            int i  = tid + it * 256;       // 0..511 (float4 index)
            int r  = i >> 2;               // 0..127
            int c4 = (i & 3) << 2;         // 0,4,8,12
            float4 va = *(const float4*)(A + (size_t)(bm + r) * K + k0 + c4);
            As[(c4 + 0) * BM + r] = va.x;
            As[(c4 + 1) * BM + r] = va.y;
            As[(c4 + 2) * BM + r] = va.z;
            As[(c4 + 3) * BM + r] = va.w;
            float4 vb = *(const float4*)(B + (size_t)(bn + r) * K + k0 + c4);
            Bs[(c4 + 0) * BN + r] = vb.x;
            Bs[(c4 + 1) * BN + r] = vb.y;
            Bs[(c4 + 2) * BN + r] = vb.z;
            Bs[(c4 + 3) * BN + r] = vb.w;
        }
        __syncthreads();

#pragma unroll
        for (int k = 0; k < BK; k++) {
            float4 a0 = *(const float4*)&As[k * BM + ty * 8];
            float4 a1 = *(const float4*)&As[k * BM + ty * 8 + 4];
            float4 b0 = *(const float4*)&Bs[k * BN + tx * 8];
            float4 b1 = *(const float4*)&Bs[k * BN + tx * 8 + 4];
            float a[8] = {a0.x, a0.y, a0.z, a0.w, a1.x, a1.y, a1.z, a1.w};
            float b[8] = {b0.x, b0.y, b0.z, b0.w, b1.x, b1.y, b1.z, b1.w};
#pragma unroll
            for (int i = 0; i < 8; i++)
#pragma unroll
                for (int j = 0; j < 8; j++) acc[i][j] += a[i] * b[j];
        }
        __syncthreads();
    }

#pragma unroll
    for (int i = 0; i < 8; i++) {
        int row = bm + ty * 8 + i;
        float* crow = C + (size_t)row * Ncols + bn + tx * 8;
#pragma unroll
        for (int j = 0; j < 8; j += 4) {
            float4 v = make_float4(acc[i][j], acc[i][j + 1], acc[i][j + 2], acc[i][j + 3]);
            if (RESIDUAL) {
                float4 rr = *(const float4*)(A + (size_t)row * K + bn + tx * 8 + j);
                v.x += rr.x; v.y += rr.y; v.z += rr.z; v.w += rr.w;
            }
            *(float4*)(crow + j) = v;
        }
    }
}

// ---------------------------------------------------------------------------
// Flash attention, fp32, 8x8 microtiles (LDS/FMA-balanced).
// One block = 128 query rows of one (n,h). 128 threads: ty=tid>>3 (16 row
// groups of 8), tx=tid&7 (8 col groups of 8). Streams 32 KV tiles of 64.
// Q pre-scaled by 0.125. Online softmax reduced across 8 tx lanes.
// K tile reads are SCALAR (odd stride 65 => conflict-free, 4B aligned).
// ---------------------------------------------------------------------------
#define BQ 128
#define BKV 64
#define KT_STRIDE 65   // padded stride for transposed K tile (odd: scalar access only!)

// dynamic smem (floats): Qs[128*64] Kts[64*65] Vs[64*64] Ps[128*64]
#define FLASH_SMEM_FLOATS (BQ * 64 + 64 * KT_STRIDE + 64 * 64 + BQ * 64)
#define FLASH_SMEM_BYTES (FLASH_SMEM_FLOATS * 4)

__global__ __launch_bounds__(128, 2) void flash_attn(const float* __restrict__ Q) {
    extern __shared__ float sm[];
    float* Qs  = sm;                       // [row][d]
    float* Kts = Qs + BQ * 64;             // [d][tok] padded (stride 65)
    float* Vs  = Kts + 64 * KT_STRIDE;     // [tok][d]
    float* Ps  = Vs + 64 * 64;             // [row][tok]

    const int tid = threadIdx.x;
    const int tx = tid & 7;        // 0..7
    const int ty = tid >> 3;       // 0..15
    const int r0 = ty * 8;         // query-row offset (0..120)
    const int c0 = tx * 8;         // kv-token / head-dim column offset (0..56)

    const int qt = blockIdx.x;             // query tile (0..15)
    const int nh = blockIdx.y;             // n*H + h (0..31)
    const int n = nh >> 3;
    const int h = nh & 7;

    const float* Qbase = Q      + (size_t)n * TT * DD + (size_t)(qt * BQ) * DD + h * HDIM;
    const float* Kbase = g_keys + (size_t)n * TT * DD + h * HDIM;
    const float* Vbase = g_vals + (size_t)n * TT * DD + h * HDIM;

    // Load Q tile (float4, pre-scaled). 128*16 float4 / 128 thr = 16 each.
    for (int i = tid; i < BQ * 16; i += 128) {
        int r = i >> 4, d4 = (i & 15) << 2;
        float4 v = *(const float4*)(Qbase + (size_t)r * DD + d4);
        v.x *= 0.125f; v.y *= 0.125f; v.z *= 0.125f; v.w *= 0.125f;
        *(float4*)&Qs[r * 64 + d4] = v;
    }

    float m[8], l[8], o[8][8];
#pragma unroll
    for (int i = 0; i < 8; i++) {
        m[i] = -1e30f;
        l[i] = 0.f;
#pragma unroll
        for (int j = 0; j < 8; j++) o[i][j] = 0.f;
    }

    for (int kt = 0; kt < TT / BKV; kt++) {
        const float* Kt = Kbase + (size_t)(kt * BKV) * DD;
        const float* Vt = Vbase + (size_t)(kt * BKV) * DD;

        __syncthreads();   // prior iter's PV reads of Vs done; Qs ready (iter 0)
        // K transposed (padded, scalar scatter), V row-major (float4 direct).
        for (int i = tid; i < BKV * 16; i += 128) {
            int tok = i >> 4, d4 = (i & 15) << 2;
            float4 kv = *(const float4*)(Kt + (size_t)tok * DD + d4);
            Kts[(d4 + 0) * KT_STRIDE + tok] = kv.x;
            Kts[(d4 + 1) * KT_STRIDE + tok] = kv.y;
            Kts[(d4 + 2) * KT_STRIDE + tok] = kv.z;
            Kts[(d4 + 3) * KT_STRIDE + tok] = kv.w;
            *(float4*)&Vs[tok * 64 + d4] = *(const float4*)(Vt + (size_t)tok * DD + d4);
        }
        __syncthreads();

        // S = Qs @ Kts   (8x8 per thread; q loads broadcast across tx lanes)
        float s[8][8];
#pragma unroll
        for (int i = 0; i < 8; i++)
#pragma unroll
            for (int j = 0; j < 8; j++) s[i][j] = 0.f;

        for (int d4 = 0; d4 < HDIM; d4 += 4) {
            float qa[8][4];
#pragma unroll
            for (int i = 0; i < 8; i++) {
                float4 t = *(const float4*)&Qs[(r0 + i) * 64 + d4];
                qa[i][0] = t.x; qa[i][1] = t.y; qa[i][2] = t.z; qa[i][3] = t.w;
            }
#pragma unroll
            for (int u = 0; u < 4; u++) {
                const float* krow = &Kts[(d4 + u) * KT_STRIDE + c0];
                float kb[8];
#pragma unroll
                for (int j = 0; j < 8; j++) kb[j] = krow[j];   // scalar, conflict-free
#pragma unroll
                for (int i = 0; i < 8; i++)
#pragma unroll
                    for (int j = 0; j < 8; j++) s[i][j] += qa[i][u] * kb[j];
            }
        }

        // Online softmax (per row, reduced across the 8 tx lanes)
#pragma unroll
        for (int i = 0; i < 8; i++) {
            float rm = s[i][0];
#pragma unroll
            for (int j = 1; j < 8; j++) rm = fmaxf(rm, s[i][j]);
            rm = fmaxf(rm, __shfl_xor_sync(0xffffffffu, rm, 1, 8));
            rm = fmaxf(rm, __shfl_xor_sync(0xffffffffu, rm, 2, 8));
            rm = fmaxf(rm, __shfl_xor_sync(0xffffffffu, rm, 4, 8));
            float mn = fmaxf(m[i], rm);
            float corr = __expf(m[i] - mn);
            float ps = 0.f;
#pragma unroll
            for (int j = 0; j < 8; j++) {
                s[i][j] = __expf(s[i][j] - mn);
                ps += s[i][j];
            }
            ps += __shfl_xor_sync(0xffffffffu, ps, 1, 8);
            ps += __shfl_xor_sync(0xffffffffu, ps, 2, 8);
            ps += __shfl_xor_sync(0xffffffffu, ps, 4, 8);
            l[i] = l[i] * corr + ps;
            m[i] = mn;
#pragma unroll
            for (int j = 0; j < 8; j++) o[i][j] *= corr;
        }

        // Stage P tile (explicit make_float4: no local-array reinterpret)
#pragma unroll
        for (int i = 0; i < 8; i++) {
            *(float4*)&Ps[(r0 + i) * 64 + c0] =
                make_float4(s[i][0], s[i][1], s[i][2], s[i][3]);
            *(float4*)&Ps[(r0 + i) * 64 + c0 + 4] =
                make_float4(s[i][4], s[i][5], s[i][6], s[i][7]);
        }
        __syncthreads();

        // O += P @ V   (p loads broadcast across tx lanes)
        for (int t4 = 0; t4 < BKV; t4 += 4) {
            float pa[8][4];
#pragma unroll
            for (int i = 0; i < 8; i++) {
                float4 t = *(const float4*)&Ps[(r0 + i) * 64 + t4];
                pa[i][0] = t.x; pa[i][1] = t.y; pa[i][2] = t.z; pa[i][3] = t.w;
            }
#pragma unroll
            for (int u = 0; u < 4; u++) {
                const float* vrow = &Vs[(t4 + u) * 64 + c0];
                float4 v0 = *(const float4*)(vrow);
                float4 v1 = *(const float4*)(vrow + 4);
                float vb[8] = {v0.x, v0.y, v0.z, v0.w, v1.x, v1.y, v1.z, v1.w};
#pragma unroll
                for (int i = 0; i < 8; i++)
#pragma unroll
                    for (int j = 0; j < 8; j++) o[i][j] += pa[i][u] * vb[j];
            }
        }
    }

    // Epilogue: normalize and store head output (concat layout)
    float* Ob = g_attn + (size_t)n * TT * DD + (size_t)(qt * BQ) * DD + h * HDIM;
#pragma unroll
    for (int i = 0; i < 8; i++) {
        float inv = 1.0f / l[i];
        *(float4*)&Ob[(size_t)(r0 + i) * DD + c0] =
            make_float4(o[i][0] * inv, o[i][1] * inv, o[i][2] * inv, o[i][3] * inv);
        *(float4*)&Ob[(size_t)(r0 + i) * DD + c0 + 4] =
            make_float4(o[i][4] * inv, o[i][5] * inv, o[i][6] * inv, o[i][7] * inv);
    }
}

// ---------------------------------------------------------------------------
// Launch
// ---------------------------------------------------------------------------
extern "C" void kernel_launch(void* const* d_in, const int* in_sizes, int n_in,
                              void* d_out, int out_size) {
    const float* q  = (const float*)d_in[0];
    const float* Wk = (const float*)d_in[1];
    const float* Wv = (const float*)d_in[2];
    const float* Wo = (const float*)d_in[3];
    float* out = (float*)d_out;

    float *keys, *vals, *attn;
    cudaGetSymbolAddress((void**)&keys, g_keys);
    cudaGetSymbolAddress((void**)&vals, g_vals);
    cudaGetSymbolAddress((void**)&attn, g_attn);

    dim3 gGemm(MROWS / 128, DD / 128);   // (64, 4)

    // keys = q @ Wk^T + q ; vals = q @ Wv^T
    sgemm_nt<true ><<<gGemm, 256>>>(q, Wk, keys, DD, DD);
    sgemm_nt<false><<<gGemm, 256>>>(q, Wv, vals, DD, DD);

    // flash attention over heads
    cudaFuncSetAttribute(flash_attn, cudaFuncAttributeMaxDynamicSharedMemorySize,
                         FLASH_SMEM_BYTES);
    dim3 gFlash(TT / BQ, NB * HH);       // (16, 32)
    flash_attn<<<gFlash, 128, FLASH_SMEM_BYTES>>>(q);

    // out = attn @ Wo^T
    sgemm_nt<false><<<gGemm, 256>>>(attn, Wo, out, DD, DD);
}

// round 5
// speedup vs baseline: 1.8566x; 1.7602x over previous
#include <cuda_runtime.h>

// Problem constants
#define NB 4
#define TT 2048
#define DD 512
#define HH 8
#define HDIM 64
#define MROWS (NB * TT)   // 8192

// Scratch (allocation-free: __device__ globals)
__device__ float g_keys[NB * TT * DD];
__device__ float g_vals[NB * TT * DD];
__device__ float g_attn[NB * TT * DD];

// ---------------------------------------------------------------------------
// fp32 -> tf32 (round-to-nearest-even on the 10-bit mantissa), bits in a u32.
// ---------------------------------------------------------------------------
__device__ __forceinline__ unsigned f2tf(float x) {
    unsigned r;
    asm("cvt.rna.tf32.f32 %0, %1;" : "=r"(r) : "f"(x));
    return r;
}
__device__ __forceinline__ float f2tf_f(float x) { return __uint_as_float(f2tf(x)); }

// mma.sync m16n8k8 tf32, fp32 accumulate (D = A*B + D)
__device__ __forceinline__ void mma_tf32(float& c0, float& c1, float& c2, float& c3,
                                         unsigned a0, unsigned a1, unsigned a2, unsigned a3,
                                         unsigned b0, unsigned b1) {
    asm volatile(
        "mma.sync.aligned.m16n8k8.row.col.f32.tf32.tf32.f32 "
        "{%0,%1,%2,%3}, {%4,%5,%6,%7}, {%8,%9}, {%0,%1,%2,%3};"
        : "+f"(c0), "+f"(c1), "+f"(c2), "+f"(c3)
        : "r"(a0), "r"(a1), "r"(a2), "r"(a3), "r"(b0), "r"(b1));
}

// ---------------------------------------------------------------------------
// SGEMM NT: C[M,Nc] = A[M,K] @ B[Nc,K]^T  (+ optional residual A[M,Nc])
// BM=BN=128, BK=16, 256 threads, 8x8 per-thread microtile. (proven R2/R4)
// ---------------------------------------------------------------------------
template <bool RESIDUAL>
__global__ __launch_bounds__(256, 2) void sgemm_nt(const float* __restrict__ A,
                                                   const float* __restrict__ B,
                                                   float* __restrict__ C,
                                                   int K, int Ncols) {
    constexpr int BM = 128, BN = 128, BK = 16;
    __shared__ float As[BK * BM];
    __shared__ float Bs[BK * BN];

    const int tid = threadIdx.x;
    const int tx = tid & 15;
    const int ty = tid >> 4;
    const int bm = blockIdx.x * BM;
    const int bn = blockIdx.y * BN;

    float acc[8][8];
#pragma unroll
    for (int i = 0; i < 8; i++)
#pragma unroll
        for (int j = 0; j < 8; j++) acc[i][j] = 0.f;

    for (int k0 = 0; k0 < K; k0 += BK) {
#pragma unroll
        for (int it = 0; it < 2; it++) {
            int i  = tid + it * 256;
            int r  = i >> 2;
            int c4 = (i & 3) << 2;
            float4 va = *(const float4*)(A + (size_t)(bm + r) * K + k0 + c4);
            As[(c4 + 0) * BM + r] = va.x;
            As[(c4 + 1) * BM + r] = va.y;
            As[(c4 + 2) * BM + r] = va.z;
            As[(c4 + 3) * BM + r] = va.w;
            float4 vb = *(const float4*)(B + (size_t)(bn + r) * K + k0 + c4);
            Bs[(c4 + 0) * BN + r] = vb.x;
            Bs[(c4 + 1) * BN + r] = vb.y;
            Bs[(c4 + 2) * BN + r] = vb.z;
            Bs[(c4 + 3) * BN + r] = vb.w;
        }
        __syncthreads();

#pragma unroll
        for (int k = 0; k < BK; k++) {
            float4 a0 = *(const float4*)&As[k * BM + ty * 8];
            float4 a1 = *(const float4*)&As[k * BM + ty * 8 + 4];
            float4 b0 = *(const float4*)&Bs[k * BN + tx * 8];
            float4 b1 = *(const float4*)&Bs[k * BN + tx * 8 + 4];
            float a[8] = {a0.x, a0.y, a0.z, a0.w, a1.x, a1.y, a1.z, a1.w};
            float b[8] = {b0.x, b0.y, b0.z, b0.w, b1.x, b1.y, b1.z, b1.w};
#pragma unroll
            for (int i = 0; i < 8; i++)
#pragma unroll
                for (int j = 0; j < 8; j++) acc[i][j] += a[i] * b[j];
        }
        __syncthreads();
    }

#pragma unroll
    for (int i = 0; i < 8; i++) {
        int row = bm + ty * 8 + i;
        float* crow = C + (size_t)row * Ncols + bn + tx * 8;
#pragma unroll
        for (int j = 0; j < 8; j += 4) {
            float4 v = make_float4(acc[i][j], acc[i][j + 1], acc[i][j + 2], acc[i][j + 3]);
            if (RESIDUAL) {
                float4 rr = *(const float4*)(A + (size_t)row * K + bn + tx * 8 + j);
                v.x += rr.x; v.y += rr.y; v.z += rr.z; v.w += rr.w;
            }
            *(float4*)(crow + j) = v;
        }
    }
}

// ---------------------------------------------------------------------------
// Flash attention on tensor cores (tf32 mma, fp32 accumulate).
// Block: 256 threads = 8 warps, BQ=128 query rows (16 per warp), one (n,h).
// Streams 32 KV tiles of BKV=64 tokens. S and O live in mma C-fragments.
// Smem row stride 68 (== 4 mod 32): conflict-free fragment LDS.
// P goes through a warp-private smem slab (only __syncwarp needed).
// ---------------------------------------------------------------------------
#define BQ 128
#define BKV 64
#define FSTR 68   // smem row stride (floats)

// Qs[128*68] Ks[64*68] Vs[64*68] Ps[128*68]
#define FLASH_SMEM_FLOATS (FSTR * (BQ + BKV + BKV + BQ))
#define FLASH_SMEM_BYTES (FLASH_SMEM_FLOATS * 4)

__global__ __launch_bounds__(256, 2) void flash_attn_tc(const float* __restrict__ Q) {
    extern __shared__ float sm[];
    float* Qs = sm;                     // [qrow][d]    (tf32 bits)
    float* Ks = Qs + BQ * FSTR;         // [tok][d]     (tf32 bits)
    float* Vs = Ks + BKV * FSTR;        // [tok][d]     (tf32 bits)
    float* Ps = Vs + BKV * FSTR;        // [qrow][tok]  (tf32 bits), warp-private slabs

    const int tid  = threadIdx.x;
    const int lane = tid & 31;
    const int wid  = tid >> 5;          // 0..7
    const int l4   = lane & 3;          // threadID in group
    const int g    = lane >> 2;         // group id (row within half-tile)
    const int wb   = wid * 16;          // warp's query-row base inside tile

    const int qt = blockIdx.x;          // query tile (0..15)
    const int nh = blockIdx.y;          // n*H + h
    const int n  = nh >> 3;
    const int h  = nh & 7;

    const float* Qbase = Q      + (size_t)n * TT * DD + (size_t)(qt * BQ) * DD + h * HDIM;
    const float* Kbase = g_keys + (size_t)n * TT * DD + h * HDIM;
    const float* Vbase = g_vals + (size_t)n * TT * DD + h * HDIM;

    // Load Q tile, pre-scale by 1/sqrt(HD)=0.125, convert to tf32.
    for (int i = tid; i < BQ * 16; i += 256) {
        int r = i >> 4, d4 = (i & 15) << 2;
        float4 v = *(const float4*)(Qbase + (size_t)r * DD + d4);
        *(float4*)&Qs[r * FSTR + d4] =
            make_float4(f2tf_f(v.x * 0.125f), f2tf_f(v.y * 0.125f),
                        f2tf_f(v.z * 0.125f), f2tf_f(v.w * 0.125f));
    }

    // Softmax state for this thread's two rows (wb+g, wb+g+8)
    float m1 = -1e30f, m2 = -1e30f, l1 = 0.f, l2 = 0.f;
    float oc[8][4];   // O fragments: 8 n-subtiles x 4 (64 head dims)
#pragma unroll
    for (int nt = 0; nt < 8; nt++)
#pragma unroll
        for (int j = 0; j < 4; j++) oc[nt][j] = 0.f;

    for (int kt = 0; kt < TT / BKV; kt++) {
        const float* Kt = Kbase + (size_t)(kt * BKV) * DD;
        const float* Vt = Vbase + (size_t)(kt * BKV) * DD;

        __syncthreads();   // previous PV reads of Ks/Vs done (and Qs ready, iter 0)
        for (int i = tid; i < BKV * 16; i += 256) {
            int tok = i >> 4, d4 = (i & 15) << 2;
            float4 kv = *(const float4*)(Kt + (size_t)tok * DD + d4);
            *(float4*)&Ks[tok * FSTR + d4] =
                make_float4(f2tf_f(kv.x), f2tf_f(kv.y), f2tf_f(kv.z), f2tf_f(kv.w));
            float4 vv = *(const float4*)(Vt + (size_t)tok * DD + d4);
            *(float4*)&Vs[tok * FSTR + d4] =
                make_float4(f2tf_f(vv.x), f2tf_f(vv.y), f2tf_f(vv.z), f2tf_f(vv.w));
        }
        __syncthreads();

        // ---- S = Q @ K^T : M16 x N64 x K64 per warp -> 8 ksteps x 8 ntiles
        float sc[8][4];
#pragma unroll
        for (int nt = 0; nt < 8; nt++)
#pragma unroll
            for (int j = 0; j < 4; j++) sc[nt][j] = 0.f;

#pragma unroll
        for (int k = 0; k < 8; k++) {
            int qa = (wb + g) * FSTR + k * 8 + l4;
            unsigned a0 = __float_as_uint(Qs[qa]);
            unsigned a1 = __float_as_uint(Qs[qa + 8 * FSTR]);
            unsigned a2 = __float_as_uint(Qs[qa + 4]);
            unsigned a3 = __float_as_uint(Qs[qa + 8 * FSTR + 4]);
#pragma unroll
            for (int nt = 0; nt < 8; nt++) {
                int kb = (nt * 8 + g) * FSTR + k * 8 + l4;   // B[k=d][n=tok] = K[tok][d]
                unsigned b0 = __float_as_uint(Ks[kb]);
                unsigned b1 = __float_as_uint(Ks[kb + 4]);
                mma_tf32(sc[nt][0], sc[nt][1], sc[nt][2], sc[nt][3],
                         a0, a1, a2, a3, b0, b1);
            }
        }

        // ---- Online softmax on fragments (rows wb+g and wb+g+8)
        float rmax1 = -1e30f, rmax2 = -1e30f;
#pragma unroll
        for (int nt = 0; nt < 8; nt++) {
            rmax1 = fmaxf(rmax1, fmaxf(sc[nt][0], sc[nt][1]));
            rmax2 = fmaxf(rmax2, fmaxf(sc[nt][2], sc[nt][3]));
        }
        rmax1 = fmaxf(rmax1, __shfl_xor_sync(0xffffffffu, rmax1, 1, 4));
        rmax1 = fmaxf(rmax1, __shfl_xor_sync(0xffffffffu, rmax1, 2, 4));
        rmax2 = fmaxf(rmax2, __shfl_xor_sync(0xffffffffu, rmax2, 1, 4));
        rmax2 = fmaxf(rmax2, __shfl_xor_sync(0xffffffffu, rmax2, 2, 4));

        float mn1 = fmaxf(m1, rmax1), mn2 = fmaxf(m2, rmax2);
        float corr1 = __expf(m1 - mn1), corr2 = __expf(m2 - mn2);

        float sum1 = 0.f, sum2 = 0.f;
#pragma unroll
        for (int nt = 0; nt < 8; nt++) {
            float p0 = __expf(sc[nt][0] - mn1);
            float p1 = __expf(sc[nt][1] - mn1);
            float p2 = __expf(sc[nt][2] - mn2);
            float p3 = __expf(sc[nt][3] - mn2);
            sum1 += p0 + p1;
            sum2 += p2 + p3;
            // stage P (tf32) into warp-private slab
            *(float2*)&Ps[(wb + g) * FSTR + nt * 8 + 2 * l4] =
                make_float2(f2tf_f(p0), f2tf_f(p1));
            *(float2*)&Ps[(wb + g + 8) * FSTR + nt * 8 + 2 * l4] =
                make_float2(f2tf_f(p2), f2tf_f(p3));
        }
        sum1 += __shfl_xor_sync(0xffffffffu, sum1, 1, 4);
        sum1 += __shfl_xor_sync(0xffffffffu, sum1, 2, 4);
        sum2 += __shfl_xor_sync(0xffffffffu, sum2, 1, 4);
        sum2 += __shfl_xor_sync(0xffffffffu, sum2, 2, 4);

        l1 = l1 * corr1 + sum1;  m1 = mn1;
        l2 = l2 * corr2 + sum2;  m2 = mn2;
#pragma unroll
        for (int nt = 0; nt < 8; nt++) {
            oc[nt][0] *= corr1; oc[nt][1] *= corr1;
            oc[nt][2] *= corr2; oc[nt][3] *= corr2;
        }

        __syncwarp();   // P slab is warp-private: warp-level sync suffices

        // ---- O += P @ V : M16 x N64 x K64(tokens) -> 8 ksteps x 8 ntiles
#pragma unroll
        for (int k = 0; k < 8; k++) {
            int pa = (wb + g) * FSTR + k * 8 + l4;
            unsigned a0 = __float_as_uint(Ps[pa]);
            unsigned a1 = __float_as_uint(Ps[pa + 8 * FSTR]);
            unsigned a2 = __float_as_uint(Ps[pa + 4]);
            unsigned a3 = __float_as_uint(Ps[pa + 8 * FSTR + 4]);
#pragma unroll
            for (int nt = 0; nt < 8; nt++) {
                // B[k=tok][n=d] = V[tok][d]
                unsigned b0 = __float_as_uint(Vs[(k * 8 + l4) * FSTR + nt * 8 + g]);
                unsigned b1 = __float_as_uint(Vs[(k * 8 + l4 + 4) * FSTR + nt * 8 + g]);
                mma_tf32(oc[nt][0], oc[nt][1], oc[nt][2], oc[nt][3],
                         a0, a1, a2, a3, b0, b1);
            }
        }
    }

    // ---- Epilogue: normalize, store to g_attn (concat-head layout)
    float inv1 = 1.0f / l1, inv2 = 1.0f / l2;
    float* Ob = g_attn + (size_t)n * TT * DD + (size_t)(qt * BQ) * DD + h * HDIM;
#pragma unroll
    for (int nt = 0; nt < 8; nt++) {
        *(float2*)&Ob[(size_t)(wb + g) * DD + nt * 8 + 2 * l4] =
            make_float2(oc[nt][0] * inv1, oc[nt][1] * inv1);
        *(float2*)&Ob[(size_t)(wb + g + 8) * DD + nt * 8 + 2 * l4] =
            make_float2(oc[nt][2] * inv2, oc[nt][3] * inv2);
    }
}

// ---------------------------------------------------------------------------
// Launch
// ---------------------------------------------------------------------------
extern "C" void kernel_launch(void* const* d_in, const int* in_sizes, int n_in,
                              void* d_out, int out_size) {
    const float* q  = (const float*)d_in[0];
    const float* Wk = (const float*)d_in[1];
    const float* Wv = (const float*)d_in[2];
    const float* Wo = (const float*)d_in[3];
    float* out = (float*)d_out;

    float *keys, *vals, *attn;
    cudaGetSymbolAddress((void**)&keys, g_keys);
    cudaGetSymbolAddress((void**)&vals, g_vals);
    cudaGetSymbolAddress((void**)&attn, g_attn);

    dim3 gGemm(MROWS / 128, DD / 128);   // (64, 4)

    // keys = q @ Wk^T + q ; vals = q @ Wv^T   (fp32)
    sgemm_nt<true ><<<gGemm, 256>>>(q, Wk, keys, DD, DD);
    sgemm_nt<false><<<gGemm, 256>>>(q, Wv, vals, DD, DD);

    // flash attention on tensor cores (tf32)
    cudaFuncSetAttribute(flash_attn_tc, cudaFuncAttributeMaxDynamicSharedMemorySize,
                         FLASH_SMEM_BYTES);
    dim3 gFlash(TT / BQ, NB * HH);       // (16, 32)
    flash_attn_tc<<<gFlash, 256, FLASH_SMEM_BYTES>>>(q);

    // out = attn @ Wo^T   (fp32)
    sgemm_nt<false><<<gGemm, 256>>>(attn, Wo, out, DD, DD);
}

// round 7
// speedup vs baseline: 2.7413x; 1.4766x over previous
#include <cuda_runtime.h>

// Problem constants
#define NB 4
#define TT 2048
#define DD 512
#define HH 8
#define HDIM 64
#define MROWS (NB * TT)   // 8192

// Scratch (allocation-free: __device__ globals)
__device__ float g_keys[NB * TT * DD];
__device__ float g_vals[NB * TT * DD];
__device__ float g_attn[NB * TT * DD];

// ---------------------------------------------------------------------------
// fp32 -> tf32 helpers + m16n8k8 tf32 mma (fp32 accumulate)
// ---------------------------------------------------------------------------
__device__ __forceinline__ unsigned f2tf(float x) {
    unsigned r;
    asm("cvt.rna.tf32.f32 %0, %1;" : "=r"(r) : "f"(x));
    return r;
}
__device__ __forceinline__ float f2tf_f(float x) { return __uint_as_float(f2tf(x)); }

__device__ __forceinline__ void mma_tf32(float& c0, float& c1, float& c2, float& c3,
                                         unsigned a0, unsigned a1, unsigned a2, unsigned a3,
                                         unsigned b0, unsigned b1) {
    asm volatile(
        "mma.sync.aligned.m16n8k8.row.col.f32.tf32.tf32.f32 "
        "{%0,%1,%2,%3}, {%4,%5,%6,%7}, {%8,%9}, {%0,%1,%2,%3};"
        : "+f"(c0), "+f"(c1), "+f"(c2), "+f"(c3)
        : "r"(a0), "r"(a1), "r"(a2), "r"(a3), "r"(b0), "r"(b1));
}

// ---------------------------------------------------------------------------
// Tensor-core GEMM NT (tf32): C[M,512] = A[M,512] @ B[512,512]^T (+ residual A)
// BM=BN=128, BK=32. 256 threads = 8 warps (4M x 2N), warp tile 32x64.
// Smem stride 36 (==4 mod 32): conflict-free fragment LDS.
// ---------------------------------------------------------------------------
#define GSTR 36

template <bool RESIDUAL>
__global__ __launch_bounds__(256, 2) void tgemm_nt(const float* __restrict__ A,
                                                   const float* __restrict__ B,
                                                   float* __restrict__ C) {
    constexpr int BM = 128, BN = 128, BK = 32;
    __shared__ float Asm[BM * GSTR];
    __shared__ float Bsm[BN * GSTR];

    const int tid  = threadIdx.x;
    const int lane = tid & 31;
    const int wid  = tid >> 5;
    const int l4   = lane & 3;
    const int g    = lane >> 2;
    const int wm   = (wid & 3) * 32;   // warp M base (0..96)
    const int wn   = (wid >> 2) * 64;  // warp N base (0 or 64)
    const int bm   = blockIdx.x * BM;
    const int bn   = blockIdx.y * BN;

    float c[2][8][4];
#pragma unroll
    for (int mt = 0; mt < 2; mt++)
#pragma unroll
        for (int nt = 0; nt < 8; nt++)
#pragma unroll
            for (int j = 0; j < 4; j++) c[mt][nt][j] = 0.f;

    for (int k0 = 0; k0 < DD; k0 += BK) {
        __syncthreads();   // prior ktile's fragment reads done
#pragma unroll
        for (int it = 0; it < 4; it++) {
            int i  = tid + it * 256;       // 0..1023 (float4 index)
            int r  = i >> 3;               // 0..127
            int c4 = (i & 7) << 2;         // 0..28
            float4 va = *(const float4*)(A + (size_t)(bm + r) * DD + k0 + c4);
            *(float4*)&Asm[r * GSTR + c4] =
                make_float4(f2tf_f(va.x), f2tf_f(va.y), f2tf_f(va.z), f2tf_f(va.w));
            float4 vb = *(const float4*)(B + (size_t)(bn + r) * DD + k0 + c4);
            *(float4*)&Bsm[r * GSTR + c4] =
                make_float4(f2tf_f(vb.x), f2tf_f(vb.y), f2tf_f(vb.z), f2tf_f(vb.w));
        }
        __syncthreads();

#pragma unroll
        for (int k8 = 0; k8 < BK / 8; k8++) {
            unsigned a[2][4];
#pragma unroll
            for (int mt = 0; mt < 2; mt++) {
                int base = (wm + mt * 16 + g) * GSTR + k8 * 8 + l4;
                a[mt][0] = __float_as_uint(Asm[base]);
                a[mt][1] = __float_as_uint(Asm[base + 8 * GSTR]);
                a[mt][2] = __float_as_uint(Asm[base + 4]);
                a[mt][3] = __float_as_uint(Asm[base + 8 * GSTR + 4]);
            }
#pragma unroll
            for (int nt = 0; nt < 8; nt++) {
                int bb = (wn + nt * 8 + g) * GSTR + k8 * 8 + l4;
                unsigned b0 = __float_as_uint(Bsm[bb]);
                unsigned b1 = __float_as_uint(Bsm[bb + 4]);
                mma_tf32(c[0][nt][0], c[0][nt][1], c[0][nt][2], c[0][nt][3],
                         a[0][0], a[0][1], a[0][2], a[0][3], b0, b1);
                mma_tf32(c[1][nt][0], c[1][nt][1], c[1][nt][2], c[1][nt][3],
                         a[1][0], a[1][1], a[1][2], a[1][3], b0, b1);
            }
        }
    }

    // Epilogue: fragment rows g / g+8, cols 2*l4 within each n-subtile.
#pragma unroll
    for (int mt = 0; mt < 2; mt++) {
        int r1 = bm + wm + mt * 16 + g;
        int r2 = r1 + 8;
#pragma unroll
        for (int nt = 0; nt < 8; nt++) {
            int col = bn + wn + nt * 8 + 2 * l4;
            float2 v1 = make_float2(c[mt][nt][0], c[mt][nt][1]);
            float2 v2 = make_float2(c[mt][nt][2], c[mt][nt][3]);
            if (RESIDUAL) {
                float2 q1 = *(const float2*)(A + (size_t)r1 * DD + col);
                float2 q2 = *(const float2*)(A + (size_t)r2 * DD + col);
                v1.x += q1.x; v1.y += q1.y;
                v2.x += q2.x; v2.y += q2.y;
            }
            *(float2*)(C + (size_t)r1 * DD + col) = v1;
            *(float2*)(C + (size_t)r2 * DD + col) = v2;
        }
    }
}

// ---------------------------------------------------------------------------
// Flash attention on tensor cores (tf32 mma, fp32 accumulate). (proven R5)
// ---------------------------------------------------------------------------
#define BQ 128
#define BKV 64
#define FSTR 68   // smem row stride (floats)

#define FLASH_SMEM_FLOATS (FSTR * (BQ + BKV + BKV + BQ))
#define FLASH_SMEM_BYTES (FLASH_SMEM_FLOATS * 4)

__global__ __launch_bounds__(256, 2) void flash_attn_tc(const float* __restrict__ Q) {
    extern __shared__ float sm[];
    float* Qs = sm;                     // [qrow][d]    (tf32 bits)
    float* Ks = Qs + BQ * FSTR;         // [tok][d]     (tf32 bits)
    float* Vs = Ks + BKV * FSTR;        // [tok][d]     (tf32 bits)
    float* Ps = Vs + BKV * FSTR;        // [qrow][tok]  (tf32 bits), warp-private slabs

    const int tid  = threadIdx.x;
    const int lane = tid & 31;
    const int wid  = tid >> 5;          // 0..7
    const int l4   = lane & 3;
    const int g    = lane >> 2;
    const int wb   = wid * 16;

    const int qt = blockIdx.x;
    const int nh = blockIdx.y;
    const int n  = nh >> 3;
    const int h  = nh & 7;

    const float* Qbase = Q      + (size_t)n * TT * DD + (size_t)(qt * BQ) * DD + h * HDIM;
    const float* Kbase = g_keys + (size_t)n * TT * DD + h * HDIM;
    const float* Vbase = g_vals + (size_t)n * TT * DD + h * HDIM;

    for (int i = tid; i < BQ * 16; i += 256) {
        int r = i >> 4, d4 = (i & 15) << 2;
        float4 v = *(const float4*)(Qbase + (size_t)r * DD + d4);
        *(float4*)&Qs[r * FSTR + d4] =
            make_float4(f2tf_f(v.x * 0.125f), f2tf_f(v.y * 0.125f),
                        f2tf_f(v.z * 0.125f), f2tf_f(v.w * 0.125f));
    }

    float m1 = -1e30f, m2 = -1e30f, l1 = 0.f, l2 = 0.f;
    float oc[8][4];
#pragma unroll
    for (int nt = 0; nt < 8; nt++)
#pragma unroll
        for (int j = 0; j < 4; j++) oc[nt][j] = 0.f;

    for (int kt = 0; kt < TT / BKV; kt++) {
        const float* Kt = Kbase + (size_t)(kt * BKV) * DD;
        const float* Vt = Vbase + (size_t)(kt * BKV) * DD;

        __syncthreads();
        for (int i = tid; i < BKV * 16; i += 256) {
            int tok = i >> 4, d4 = (i & 15) << 2;
            float4 kv = *(const float4*)(Kt + (size_t)tok * DD + d4);
            *(float4*)&Ks[tok * FSTR + d4] =
                make_float4(f2tf_f(kv.x), f2tf_f(kv.y), f2tf_f(kv.z), f2tf_f(kv.w));
            float4 vv = *(const float4*)(Vt + (size_t)tok * DD + d4);
            *(float4*)&Vs[tok * FSTR + d4] =
                make_float4(f2tf_f(vv.x), f2tf_f(vv.y), f2tf_f(vv.z), f2tf_f(vv.w));
        }
        __syncthreads();

        float sc[8][4];
#pragma unroll
        for (int nt = 0; nt < 8; nt++)
#pragma unroll
            for (int j = 0; j < 4; j++) sc[nt][j] = 0.f;

#pragma unroll
        for (int k = 0; k < 8; k++) {
            int qa = (wb + g) * FSTR + k * 8 + l4;
            unsigned a0 = __float_as_uint(Qs[qa]);
            unsigned a1 = __float_as_uint(Qs[qa + 8 * FSTR]);
            unsigned a2 = __float_as_uint(Qs[qa + 4]);
            unsigned a3 = __float_as_uint(Qs[qa + 8 * FSTR + 4]);
#pragma unroll
            for (int nt = 0; nt < 8; nt++) {
                int kb = (nt * 8 + g) * FSTR + k * 8 + l4;
                unsigned b0 = __float_as_uint(Ks[kb]);
                unsigned b1 = __float_as_uint(Ks[kb + 4]);
                mma_tf32(sc[nt][0], sc[nt][1], sc[nt][2], sc[nt][3],
                         a0, a1, a2, a3, b0, b1);
            }
        }

        float rmax1 = -1e30f, rmax2 = -1e30f;
#pragma unroll
        for (int nt = 0; nt < 8; nt++) {
            rmax1 = fmaxf(rmax1, fmaxf(sc[nt][0], sc[nt][1]));
            rmax2 = fmaxf(rmax2, fmaxf(sc[nt][2], sc[nt][3]));
        }
        rmax1 = fmaxf(rmax1, __shfl_xor_sync(0xffffffffu, rmax1, 1, 4));
        rmax1 = fmaxf(rmax1, __shfl_xor_sync(0xffffffffu, rmax1, 2, 4));
        rmax2 = fmaxf(rmax2, __shfl_xor_sync(0xffffffffu, rmax2, 1, 4));
        rmax2 = fmaxf(rmax2, __shfl_xor_sync(0xffffffffu, rmax2, 2, 4));

        float mn1 = fmaxf(m1, rmax1), mn2 = fmaxf(m2, rmax2);
        float corr1 = __expf(m1 - mn1), corr2 = __expf(m2 - mn2);

        float sum1 = 0.f, sum2 = 0.f;
#pragma unroll
        for (int nt = 0; nt < 8; nt++) {
            float p0 = __expf(sc[nt][0] - mn1);
            float p1 = __expf(sc[nt][1] - mn1);
            float p2 = __expf(sc[nt][2] - mn2);
            float p3 = __expf(sc[nt][3] - mn2);
            sum1 += p0 + p1;
            sum2 += p2 + p3;
            *(float2*)&Ps[(wb + g) * FSTR + nt * 8 + 2 * l4] =
                make_float2(f2tf_f(p0), f2tf_f(p1));
            *(float2*)&Ps[(wb + g + 8) * FSTR + nt * 8 + 2 * l4] =
                make_float2(f2tf_f(p2), f2tf_f(p3));
        }
        sum1 += __shfl_xor_sync(0xffffffffu, sum1, 1, 4);
        sum1 += __shfl_xor_sync(0xffffffffu, sum1, 2, 4);
        sum2 += __shfl_xor_sync(0xffffffffu, sum2, 1, 4);
        sum2 += __shfl_xor_sync(0xffffffffu, sum2, 2, 4);

        l1 = l1 * corr1 + sum1;  m1 = mn1;
        l2 = l2 * corr2 + sum2;  m2 = mn2;
#pragma unroll
        for (int nt = 0; nt < 8; nt++) {
            oc[nt][0] *= corr1; oc[nt][1] *= corr1;
            oc[nt][2] *= corr2; oc[nt][3] *= corr2;
        }

        __syncwarp();

#pragma unroll
        for (int k = 0; k < 8; k++) {
            int pa = (wb + g) * FSTR + k * 8 + l4;
            unsigned a0 = __float_as_uint(Ps[pa]);
            unsigned a1 = __float_as_uint(Ps[pa + 8 * FSTR]);
            unsigned a2 = __float_as_uint(Ps[pa + 4]);
            unsigned a3 = __float_as_uint(Ps[pa + 8 * FSTR + 4]);
#pragma unroll
            for (int nt = 0; nt < 8; nt++) {
                unsigned b0 = __float_as_uint(Vs[(k * 8 + l4) * FSTR + nt * 8 + g]);
                unsigned b1 = __float_as_uint(Vs[(k * 8 + l4 + 4) * FSTR + nt * 8 + g]);
                mma_tf32(oc[nt][0], oc[nt][1], oc[nt][2], oc[nt][3],
                         a0, a1, a2, a3, b0, b1);
            }
        }
    }

    float inv1 = 1.0f / l1, inv2 = 1.0f / l2;
    float* Ob = g_attn + (size_t)n * TT * DD + (size_t)(qt * BQ) * DD + h * HDIM;
#pragma unroll
    for (int nt = 0; nt < 8; nt++) {
        *(float2*)&Ob[(size_t)(wb + g) * DD + nt * 8 + 2 * l4] =
            make_float2(oc[nt][0] * inv1, oc[nt][1] * inv1);
        *(float2*)&Ob[(size_t)(wb + g + 8) * DD + nt * 8 + 2 * l4] =
            make_float2(oc[nt][2] * inv2, oc[nt][3] * inv2);
    }
}

// ---------------------------------------------------------------------------
// Launch
// ---------------------------------------------------------------------------
extern "C" void kernel_launch(void* const* d_in, const int* in_sizes, int n_in,
                              void* d_out, int out_size) {
    const float* q  = (const float*)d_in[0];
    const float* Wk = (const float*)d_in[1];
    const float* Wv = (const float*)d_in[2];
    const float* Wo = (const float*)d_in[3];
    float* out = (float*)d_out;

    float *keys, *vals, *attn;
    cudaGetSymbolAddress((void**)&keys, g_keys);
    cudaGetSymbolAddress((void**)&vals, g_vals);
    cudaGetSymbolAddress((void**)&attn, g_attn);

    dim3 gGemm(MROWS / 128, DD / 128);   // (64, 4)

    // keys = q @ Wk^T + q ; vals = q @ Wv^T   (tf32 tensor cores)
    tgemm_nt<true ><<<gGemm, 256>>>(q, Wk, keys);
    tgemm_nt<false><<<gGemm, 256>>>(q, Wv, vals);

    // flash attention on tensor cores (tf32)
    cudaFuncSetAttribute(flash_attn_tc, cudaFuncAttributeMaxDynamicSharedMemorySize,
                         FLASH_SMEM_BYTES);
    dim3 gFlash(TT / BQ, NB * HH);       // (16, 32)
    flash_attn_tc<<<gFlash, 256, FLASH_SMEM_BYTES>>>(q);

    // out = attn @ Wo^T   (tf32 tensor cores)
    tgemm_nt<false><<<gGemm, 256>>>(attn, Wo, out);
}

// round 8
// speedup vs baseline: 3.1259x; 1.1403x over previous
#include <cuda_runtime.h>

// Problem constants
#define NB 4
#define TT 2048
#define DD 512
#define HH 8
#define HDIM 64
#define MROWS (NB * TT)   // 8192

// Scratch (allocation-free: __device__ globals)
__device__ float g_keys[NB * TT * DD];   // stored tf32-RNE-rounded
__device__ float g_vals[NB * TT * DD];   // stored tf32-RNE-rounded
__device__ float g_attn[NB * TT * DD];

// ---------------------------------------------------------------------------
// fp32 -> tf32 helpers + m16n8k8 tf32 mma (fp32 accumulate)
// ---------------------------------------------------------------------------
__device__ __forceinline__ unsigned f2tf(float x) {
    unsigned r;
    asm("cvt.rna.tf32.f32 %0, %1;" : "=r"(r) : "f"(x));
    return r;
}
__device__ __forceinline__ float f2tf_f(float x) { return __uint_as_float(f2tf(x)); }

__device__ __forceinline__ void mma_tf32(float& c0, float& c1, float& c2, float& c3,
                                         unsigned a0, unsigned a1, unsigned a2, unsigned a3,
                                         unsigned b0, unsigned b1) {
    asm volatile(
        "mma.sync.aligned.m16n8k8.row.col.f32.tf32.tf32.f32 "
        "{%0,%1,%2,%3}, {%4,%5,%6,%7}, {%8,%9}, {%0,%1,%2,%3};"
        : "+f"(c0), "+f"(c1), "+f"(c2), "+f"(c3)
        : "r"(a0), "r"(a1), "r"(a2), "r"(a3), "r"(b0), "r"(b1));
}

__device__ __forceinline__ void cp_async16(unsigned saddr, const void* gptr) {
    asm volatile("cp.async.cg.shared.global [%0], [%1], 16;" :: "r"(saddr), "l"(gptr));
}

// ---------------------------------------------------------------------------
// Tensor-core GEMM NT (tf32): C[M,512] = A[M,512] @ B[512,512]^T (+ residual A)
// TF32OUT: round the stored result to tf32 (for keys/vals consumed by flash
// via raw-byte cp.async — identical numerics to converting inside flash).
// ---------------------------------------------------------------------------
#define GSTR 36

template <bool RESIDUAL, bool TF32OUT>
__global__ __launch_bounds__(256, 2) void tgemm_nt(const float* __restrict__ A,
                                                   const float* __restrict__ B,
                                                   float* __restrict__ C) {
    constexpr int BM = 128, BN = 128, BK = 32;
    __shared__ float Asm[BM * GSTR];
    __shared__ float Bsm[BN * GSTR];

    const int tid  = threadIdx.x;
    const int lane = tid & 31;
    const int wid  = tid >> 5;
    const int l4   = lane & 3;
    const int g    = lane >> 2;
    const int wm   = (wid & 3) * 32;
    const int wn   = (wid >> 2) * 64;
    const int bm   = blockIdx.x * BM;
    const int bn   = blockIdx.y * BN;

    float c[2][8][4];
#pragma unroll
    for (int mt = 0; mt < 2; mt++)
#pragma unroll
        for (int nt = 0; nt < 8; nt++)
#pragma unroll
            for (int j = 0; j < 4; j++) c[mt][nt][j] = 0.f;

    for (int k0 = 0; k0 < DD; k0 += BK) {
        __syncthreads();
#pragma unroll
        for (int it = 0; it < 4; it++) {
            int i  = tid + it * 256;
            int r  = i >> 3;
            int c4 = (i & 7) << 2;
            float4 va = *(const float4*)(A + (size_t)(bm + r) * DD + k0 + c4);
            *(float4*)&Asm[r * GSTR + c4] =
                make_float4(f2tf_f(va.x), f2tf_f(va.y), f2tf_f(va.z), f2tf_f(va.w));
            float4 vb = *(const float4*)(B + (size_t)(bn + r) * DD + k0 + c4);
            *(float4*)&Bsm[r * GSTR + c4] =
                make_float4(f2tf_f(vb.x), f2tf_f(vb.y), f2tf_f(vb.z), f2tf_f(vb.w));
        }
        __syncthreads();

#pragma unroll
        for (int k8 = 0; k8 < BK / 8; k8++) {
            unsigned a[2][4];
#pragma unroll
            for (int mt = 0; mt < 2; mt++) {
                int base = (wm + mt * 16 + g) * GSTR + k8 * 8 + l4;
                a[mt][0] = __float_as_uint(Asm[base]);
                a[mt][1] = __float_as_uint(Asm[base + 8 * GSTR]);
                a[mt][2] = __float_as_uint(Asm[base + 4]);
                a[mt][3] = __float_as_uint(Asm[base + 8 * GSTR + 4]);
            }
#pragma unroll
            for (int nt = 0; nt < 8; nt++) {
                int bb = (wn + nt * 8 + g) * GSTR + k8 * 8 + l4;
                unsigned b0 = __float_as_uint(Bsm[bb]);
                unsigned b1 = __float_as_uint(Bsm[bb + 4]);
                mma_tf32(c[0][nt][0], c[0][nt][1], c[0][nt][2], c[0][nt][3],
                         a[0][0], a[0][1], a[0][2], a[0][3], b0, b1);
                mma_tf32(c[1][nt][0], c[1][nt][1], c[1][nt][2], c[1][nt][3],
                         a[1][0], a[1][1], a[1][2], a[1][3], b0, b1);
            }
        }
    }

#pragma unroll
    for (int mt = 0; mt < 2; mt++) {
        int r1 = bm + wm + mt * 16 + g;
        int r2 = r1 + 8;
#pragma unroll
        for (int nt = 0; nt < 8; nt++) {
            int col = bn + wn + nt * 8 + 2 * l4;
            float2 v1 = make_float2(c[mt][nt][0], c[mt][nt][1]);
            float2 v2 = make_float2(c[mt][nt][2], c[mt][nt][3]);
            if (RESIDUAL) {
                float2 q1 = *(const float2*)(A + (size_t)r1 * DD + col);
                float2 q2 = *(const float2*)(A + (size_t)r2 * DD + col);
                v1.x += q1.x; v1.y += q1.y;
                v2.x += q2.x; v2.y += q2.y;
            }
            if (TF32OUT) {
                v1.x = f2tf_f(v1.x); v1.y = f2tf_f(v1.y);
                v2.x = f2tf_f(v2.x); v2.y = f2tf_f(v2.y);
            }
            *(float2*)(C + (size_t)r1 * DD + col) = v1;
            *(float2*)(C + (size_t)r2 * DD + col) = v2;
        }
    }
}

// ---------------------------------------------------------------------------
// Flash attention on tensor cores (tf32 mma, fp32 accumulate).
// R8: Q fragments hoisted to registers (Qs smem reused as P slab),
//     K/V double-buffered via cp.async (inputs pre-rounded to tf32),
//     softmax in exp2 domain (log2e folded into Q pre-scale).
// ---------------------------------------------------------------------------
#define BQ 128
#define BKV 64
#define FSTR 68   // smem row stride (floats)
#define NKT (TT / BKV)   // 32 KV tiles

// Qp(=Ps)[128] Ks0[64] Ks1[64] Vs0[64] Vs1[64] rows of FSTR floats
#define FLASH_SMEM_FLOATS (FSTR * (BQ + 4 * BKV))
#define FLASH_SMEM_BYTES (FLASH_SMEM_FLOATS * 4)

__global__ __launch_bounds__(256, 2) void flash_attn_tc(const float* __restrict__ Q) {
    extern __shared__ float sm[];
    float* Qp  = sm;                      // Q staging, then P slab (warp-private rows)
    float* Ks0 = Qp  + BQ  * FSTR;
    float* Ks1 = Ks0 + BKV * FSTR;
    float* Vs0 = Ks1 + BKV * FSTR;
    float* Vs1 = Vs0 + BKV * FSTR;

    const unsigned ks0u = (unsigned)__cvta_generic_to_shared(Ks0);
    const unsigned ks1u = (unsigned)__cvta_generic_to_shared(Ks1);
    const unsigned vs0u = (unsigned)__cvta_generic_to_shared(Vs0);
    const unsigned vs1u = (unsigned)__cvta_generic_to_shared(Vs1);

    const int tid  = threadIdx.x;
    const int lane = tid & 31;
    const int wid  = tid >> 5;
    const int l4   = lane & 3;
    const int g    = lane >> 2;
    const int wb   = wid * 16;

    const int qt = blockIdx.x;
    const int nh = blockIdx.y;
    const int n  = nh >> 3;
    const int h  = nh & 7;

    const float* Qbase = Q      + (size_t)n * TT * DD + (size_t)(qt * BQ) * DD + h * HDIM;
    const float* Kbase = g_keys + (size_t)n * TT * DD + h * HDIM;
    const float* Vbase = g_vals + (size_t)n * TT * DD + h * HDIM;

    // Q tile: pre-scale by (1/sqrt(HD)) * log2(e) for exp2-domain softmax.
    const float QSCALE = 0.125f * 1.44269504088896341f;
    for (int i = tid; i < BQ * 16; i += 256) {
        int r = i >> 4, d4 = (i & 15) << 2;
        float4 v = *(const float4*)(Qbase + (size_t)r * DD + d4);
        *(float4*)&Qp[r * FSTR + d4] =
            make_float4(f2tf_f(v.x * QSCALE), f2tf_f(v.y * QSCALE),
                        f2tf_f(v.z * QSCALE), f2tf_f(v.w * QSCALE));
    }

    // Prologue: async-load KV tile 0 into buffer 0 (K/V already tf32 bits).
#pragma unroll
    for (int it = 0; it < 4; it++) {
        int i = tid + it * 256;
        int tok = i >> 4, d4 = (i & 15) << 2;
        unsigned off = (unsigned)(tok * FSTR + d4) * 4u;
        cp_async16(ks0u + off, Kbase + (size_t)tok * DD + d4);
        cp_async16(vs0u + off, Vbase + (size_t)tok * DD + d4);
    }
    asm volatile("cp.async.commit_group;");

    __syncthreads();   // Qp staging complete

    // Hoist Q fragments (loop-invariant): 8 ksteps x 4 regs.
    unsigned qf[8][4];
#pragma unroll
    for (int k = 0; k < 8; k++) {
        int qa = (wb + g) * FSTR + k * 8 + l4;
        qf[k][0] = __float_as_uint(Qp[qa]);
        qf[k][1] = __float_as_uint(Qp[qa + 8 * FSTR]);
        qf[k][2] = __float_as_uint(Qp[qa + 4]);
        qf[k][3] = __float_as_uint(Qp[qa + 8 * FSTR + 4]);
    }

    float m1 = -1e30f, m2 = -1e30f, l1 = 0.f, l2 = 0.f;
    float oc[8][4];
#pragma unroll
    for (int nt = 0; nt < 8; nt++)
#pragma unroll
        for (int j = 0; j < 4; j++) oc[nt][j] = 0.f;

    for (int kt = 0; kt < NKT; kt++) {
        const bool odd = kt & 1;
        float* Kc = odd ? Ks1 : Ks0;
        float* Vc = odd ? Vs1 : Vs0;

        if (kt + 1 < NKT) {
            // issue next tile into the other buffer, then wait for current
            unsigned knu = odd ? ks0u : ks1u;
            unsigned vnu = odd ? vs0u : vs1u;
            const float* Kt = Kbase + (size_t)((kt + 1) * BKV) * DD;
            const float* Vt = Vbase + (size_t)((kt + 1) * BKV) * DD;
#pragma unroll
            for (int it = 0; it < 4; it++) {
                int i = tid + it * 256;
                int tok = i >> 4, d4 = (i & 15) << 2;
                unsigned off = (unsigned)(tok * FSTR + d4) * 4u;
                cp_async16(knu + off, Kt + (size_t)tok * DD + d4);
                cp_async16(vnu + off, Vt + (size_t)tok * DD + d4);
            }
            asm volatile("cp.async.commit_group;");
            asm volatile("cp.async.wait_group 1;");
        } else {
            asm volatile("cp.async.wait_group 0;");
        }
        __syncthreads();   // current K/V visible to all warps

        // ---- S = Q @ K^T
        float sc[8][4];
#pragma unroll
        for (int nt = 0; nt < 8; nt++)
#pragma unroll
            for (int j = 0; j < 4; j++) sc[nt][j] = 0.f;

#pragma unroll
        for (int k = 0; k < 8; k++) {
#pragma unroll
            for (int nt = 0; nt < 8; nt++) {
                int kb = (nt * 8 + g) * FSTR + k * 8 + l4;
                unsigned b0 = __float_as_uint(Kc[kb]);
                unsigned b1 = __float_as_uint(Kc[kb + 4]);
                mma_tf32(sc[nt][0], sc[nt][1], sc[nt][2], sc[nt][3],
                         qf[k][0], qf[k][1], qf[k][2], qf[k][3], b0, b1);
            }
        }

        // ---- Online softmax (exp2 domain)
        float rmax1 = -1e30f, rmax2 = -1e30f;
#pragma unroll
        for (int nt = 0; nt < 8; nt++) {
            rmax1 = fmaxf(rmax1, fmaxf(sc[nt][0], sc[nt][1]));
            rmax2 = fmaxf(rmax2, fmaxf(sc[nt][2], sc[nt][3]));
        }
        rmax1 = fmaxf(rmax1, __shfl_xor_sync(0xffffffffu, rmax1, 1, 4));
        rmax1 = fmaxf(rmax1, __shfl_xor_sync(0xffffffffu, rmax1, 2, 4));
        rmax2 = fmaxf(rmax2, __shfl_xor_sync(0xffffffffu, rmax2, 1, 4));
        rmax2 = fmaxf(rmax2, __shfl_xor_sync(0xffffffffu, rmax2, 2, 4));

        float mn1 = fmaxf(m1, rmax1), mn2 = fmaxf(m2, rmax2);
        float corr1 = exp2f(m1 - mn1), corr2 = exp2f(m2 - mn2);

        float sum1 = 0.f, sum2 = 0.f;
#pragma unroll
        for (int nt = 0; nt < 8; nt++) {
            float p0 = exp2f(sc[nt][0] - mn1);
            float p1 = exp2f(sc[nt][1] - mn1);
            float p2 = exp2f(sc[nt][2] - mn2);
            float p3 = exp2f(sc[nt][3] - mn2);
            sum1 += p0 + p1;
            sum2 += p2 + p3;
            *(float2*)&Qp[(wb + g) * FSTR + nt * 8 + 2 * l4] =
                make_float2(f2tf_f(p0), f2tf_f(p1));
            *(float2*)&Qp[(wb + g + 8) * FSTR + nt * 8 + 2 * l4] =
                make_float2(f2tf_f(p2), f2tf_f(p3));
        }
        sum1 += __shfl_xor_sync(0xffffffffu, sum1, 1, 4);
        sum1 += __shfl_xor_sync(0xffffffffu, sum1, 2, 4);
        sum2 += __shfl_xor_sync(0xffffffffu, sum2, 1, 4);
        sum2 += __shfl_xor_sync(0xffffffffu, sum2, 2, 4);

        l1 = l1 * corr1 + sum1;  m1 = mn1;
        l2 = l2 * corr2 + sum2;  m2 = mn2;
#pragma unroll
        for (int nt = 0; nt < 8; nt++) {
            oc[nt][0] *= corr1; oc[nt][1] *= corr1;
            oc[nt][2] *= corr2; oc[nt][3] *= corr2;
        }

        __syncwarp();   // P slab is warp-private (rows wb..wb+15)

        // ---- O += P @ V
#pragma unroll
        for (int k = 0; k < 8; k++) {
            int pa = (wb + g) * FSTR + k * 8 + l4;
            unsigned a0 = __float_as_uint(Qp[pa]);
            unsigned a1 = __float_as_uint(Qp[pa + 8 * FSTR]);
            unsigned a2 = __float_as_uint(Qp[pa + 4]);
            unsigned a3 = __float_as_uint(Qp[pa + 8 * FSTR + 4]);
#pragma unroll
            for (int nt = 0; nt < 8; nt++) {
                unsigned b0 = __float_as_uint(Vc[(k * 8 + l4) * FSTR + nt * 8 + g]);
                unsigned b1 = __float_as_uint(Vc[(k * 8 + l4 + 4) * FSTR + nt * 8 + g]);
                mma_tf32(oc[nt][0], oc[nt][1], oc[nt][2], oc[nt][3],
                         a0, a1, a2, a3, b0, b1);
            }
        }
        __syncthreads();   // all warps done with current buffer before overwrite
    }

    float inv1 = 1.0f / l1, inv2 = 1.0f / l2;
    float* Ob = g_attn + (size_t)n * TT * DD + (size_t)(qt * BQ) * DD + h * HDIM;
#pragma unroll
    for (int nt = 0; nt < 8; nt++) {
        *(float2*)&Ob[(size_t)(wb + g) * DD + nt * 8 + 2 * l4] =
            make_float2(oc[nt][0] * inv1, oc[nt][1] * inv1);
        *(float2*)&Ob[(size_t)(wb + g + 8) * DD + nt * 8 + 2 * l4] =
            make_float2(oc[nt][2] * inv2, oc[nt][3] * inv2);
    }
}

// ---------------------------------------------------------------------------
// Launch
// ---------------------------------------------------------------------------
extern "C" void kernel_launch(void* const* d_in, const int* in_sizes, int n_in,
                              void* d_out, int out_size) {
    const float* q  = (const float*)d_in[0];
    const float* Wk = (const float*)d_in[1];
    const float* Wv = (const float*)d_in[2];
    const float* Wo = (const float*)d_in[3];
    float* out = (float*)d_out;

    float *keys, *vals, *attn;
    cudaGetSymbolAddress((void**)&keys, g_keys);
    cudaGetSymbolAddress((void**)&vals, g_vals);
    cudaGetSymbolAddress((void**)&attn, g_attn);

    dim3 gGemm(MROWS / 128, DD / 128);   // (64, 4)

    // keys = tf32(q @ Wk^T + q) ; vals = tf32(q @ Wv^T)
    tgemm_nt<true , true ><<<gGemm, 256>>>(q, Wk, keys);
    tgemm_nt<false, true ><<<gGemm, 256>>>(q, Wv, vals);

    // flash attention on tensor cores (tf32, cp.async double-buffered)
    cudaFuncSetAttribute(flash_attn_tc, cudaFuncAttributeMaxDynamicSharedMemorySize,
                         FLASH_SMEM_BYTES);
    dim3 gFlash(TT / BQ, NB * HH);       // (16, 32)
    flash_attn_tc<<<gFlash, 256, FLASH_SMEM_BYTES>>>(q);

    // out = attn @ Wo^T   (fp32 output, no rounding)
    tgemm_nt<false, false><<<gGemm, 256>>>(attn, Wo, out);
}